// round 11
// baseline (speedup 1.0000x reference)
#include <cuda_runtime.h>
#include <float.h>

// ROI adaptive max pool 7x7 — R5/R8 mapping + branch-free predicated bins:
// 5 static load slots per bin (@P LDG, no duplicate traffic, one basic
// block across all 7 bins -> high MLP), block-uniform residual pass for
// tall ROIs (Hr>=24).
// images: [8,256,56,56] f32; rois: [256,4] f32; roi_idx: [256] i32
// out: [256,256,7,7] f32

#define Hc 56
#define Wc 56
#define Cc 256
#define Rc 256
#define OUTN 7
#define CPB 16
#define W4 (Wc / 4)   // 14

__device__ __forceinline__ float4 fm4(float4 a, float4 b) {
    return make_float4(fmaxf(a.x, b.x), fmaxf(a.y, b.y),
                       fmaxf(a.z, b.z), fmaxf(a.w, b.w));
}

__global__ __launch_bounds__(256, 6) void roipool_kernel(
    const float* __restrict__ images,
    const float* __restrict__ rois,
    const int* __restrict__ roi_idx,
    float* __restrict__ out)
{
    __shared__ float rowp[CPB][OUTN][60];
    __shared__ int sb[28];   // ys[7] ye[7] xs[7] xe[7]

    const int r  = blockIdx.y;
    const int cg = blockIdx.x;
    const int tx = threadIdx.x;            // 0..15 quad
    const int ty = threadIdx.y;            // 0..15 channel
    const int tid = ty * 16 + tx;

    const float4 rv = ((const float4*)rois)[r];
    const int x1 = (int)floorf(rv.x * (float)Wc);
    const int y1 = (int)floorf(rv.y * (float)Hc);
    const int x2 = (int)ceilf (rv.z * (float)Wc);
    const int y2 = (int)ceilf (rv.w * (float)Hc);
    const int Hr = y2 - y1;
    const int Wr = x2 - x1;

    if (tid < 28) {
        const int g = tid / OUTN;          // 0:ys 1:ye 2:xs 3:xe
        const int i = tid - g * OUTN;
        int v;
        if (g == 0)      v = y1 + (i * Hr) / OUTN;
        else if (g == 1) v = y1 + ((i + 1) * Hr + OUTN - 1) / OUTN;
        else if (g == 2) v = x1 + (i * Wr) / OUTN;
        else             v = x1 + ((i + 1) * Wr + OUTN - 1) / OUTN;
        sb[tid] = v;
    }
    __syncthreads();

    const int n_img = roi_idx[r];
    const float* __restrict__ img =
        images + (size_t)(n_img * Cc + cg * CPB + ty) * (Hc * Wc);

    const int qlo = x1 >> 2;
    const int qhi = (x2 + 3) >> 2;
    const bool active = (tx >= qlo && tx < qhi);
    const float4* __restrict__ base = (const float4*)img + tx;

    // ---- Phase 1 main pass: 7 bins, 5 predicated load slots each,
    //      single straight-line region -> batched independent LDGs ----
    if (active) {
        #pragma unroll
        for (int i = 0; i < OUTN; i++) {
            const int s = sb[i];
            const int n = sb[7 + i] - s;   // warp-uniform, >=1
            const float4* __restrict__ p = base + s * W4;
            float4 m = p[0];
            #pragma unroll
            for (int k = 1; k < 5; k++) {
                float4 v = make_float4(-FLT_MAX, -FLT_MAX, -FLT_MAX, -FLT_MAX);
                if (k < n) v = p[k * W4];   // predicated LDG, no traffic if off
                m = fm4(m, v);
            }
            *(float4*)&rowp[ty][i][tx * 4] = m;
        }
        // ---- Residual pass: only tall ROIs (block-uniform branch) ----
        if (Hr >= 24) {
            #pragma unroll
            for (int i = 0; i < OUTN; i++) {
                const int s = sb[i];
                const int n = sb[7 + i] - s;
                if (n > 5) {
                    const float4* __restrict__ p = base + s * W4;
                    float4 m = *(float4*)&rowp[ty][i][tx * 4];
                    for (int y = 5; y < n; y++)
                        m = fm4(m, p[y * W4]);
                    *(float4*)&rowp[ty][i][tx * 4] = m;
                }
            }
        }
    }
    __syncthreads();

    // ---- Phase 2: col-bin maxes from shared, same predicated scheme ----
    float* __restrict__ outg = out + ((size_t)r * Cc + cg * CPB) * (OUTN * OUTN);
    #pragma unroll
    for (int o = tid; o < CPB * OUTN * OUTN; o += 256) {
        const int cc = o / (OUTN * OUTN);
        const int ij = o - cc * (OUTN * OUTN);
        const int i = ij / OUTN;
        const int j = ij - i * OUTN;
        const int s = sb[14 + j];
        const int n = sb[21 + j] - s;      // >=1
        const float* __restrict__ rp = &rowp[cc][i][s];
        float m = rp[0];
        #pragma unroll
        for (int k = 1; k < 5; k++) {
            float v = -FLT_MAX;
            if (k < n) v = rp[k];
            m = fmaxf(m, v);
        }
        if (Wr >= 24 && n > 5) {
            for (int x = 5; x < n; x++)
                m = fmaxf(m, rp[x]);
        }
        outg[o] = m;   // contiguous per stride-pass -> coalesced
    }
}

extern "C" void kernel_launch(void* const* d_in, const int* in_sizes, int n_in,
                              void* d_out, int out_size) {
    const float* images  = (const float*)d_in[0];
    const float* rois    = (const float*)d_in[1];
    const int*   roi_idx = (const int*)d_in[2];
    float* out = (float*)d_out;

    dim3 grid(Cc / CPB, Rc);   // (16, 256) = 4096 blocks
    dim3 block(16, 16);        // 256 threads
    roipool_kernel<<<grid, block>>>(images, rois, roi_idx, out);
}